// round 10
// baseline (speedup 1.0000x reference)
#include <cuda_runtime.h>
#include <cuda_bf16.h>
#include <cuda_fp16.h>
#include <stdint.h>

#define NNODES 50000
#define NEDGES 800000
#define MTILE 64
#define NTILES (NEDGES / MTILE)   // 12500
#define EDGE_GRID 444

typedef unsigned long long ull;

// ---------------- scratch ----------------
__device__ __align__(128) __nv_bfloat16 g_hAB[(size_t)NNODES * 256];
__device__ float g_sA[NNODES];
__device__ float g_sB[NNODES];
__device__ float g_agg[NNODES * 9];

// ---------------- helpers ----------------
static __device__ __forceinline__ uint32_t packbf(float a, float b) {
    __nv_bfloat162 h = __floats2bfloat162_rn(a, b);
    return *reinterpret_cast<uint32_t*>(&h);
}
// ---- packed f32x2 ----
static __device__ __forceinline__ ull pk2(float lo, float hi) {
    ull r; asm("mov.b64 %0, {%1, %2};" : "=l"(r) : "f"(lo), "f"(hi)); return r;
}
static __device__ __forceinline__ float2 up2(ull v) {
    float2 f; asm("mov.b64 {%0, %1}, %2;" : "=f"(f.x), "=f"(f.y) : "l"(v)); return f;
}
static __device__ __forceinline__ ull add2(ull a, ull b) {
    ull r; asm("add.rn.f32x2 %0, %1, %2;" : "=l"(r) : "l"(a), "l"(b)); return r;
}
static __device__ __forceinline__ ull mul2(ull a, ull b) {
    ull r; asm("mul.rn.f32x2 %0, %1, %2;" : "=l"(r) : "l"(a), "l"(b)); return r;
}
static __device__ __forceinline__ ull fma2(ull a, ull b, ull c) {
    ull r; asm("fma.rn.f32x2 %0, %1, %2, %3;" : "=l"(r) : "l"(a), "l"(b), "l"(c)); return r;
}
// bf16x2 word -> f32x2 (element order preserved)
static __device__ __forceinline__ ull bf2f2(uint32_t u) {
    uint32_t lo = u << 16;
    uint32_t hi = u & 0xFFFF0000u;
    ull r; asm("mov.b64 %0, {%1, %2};" : "=l"(r) : "r"(lo), "r"(hi)); return r;
}

static __device__ __forceinline__ void mma16816(float* c, const uint32_t* a, const uint32_t* b) {
    asm volatile(
        "mma.sync.aligned.m16n8k16.row.col.f32.bf16.bf16.f32 "
        "{%0,%1,%2,%3}, {%4,%5,%6,%7}, {%8,%9}, {%0,%1,%2,%3};\n"
        : "+f"(c[0]), "+f"(c[1]), "+f"(c[2]), "+f"(c[3])
        : "r"(a[0]), "r"(a[1]), "r"(a[2]), "r"(a[3]), "r"(b[0]), "r"(b[1]));
}
static __device__ __forceinline__ void ldsm4(uint32_t* r, uint32_t addr) {
    asm volatile("ldmatrix.sync.aligned.m8n8.x4.shared.b16 {%0,%1,%2,%3}, [%4];"
        : "=r"(r[0]), "=r"(r[1]), "=r"(r[2]), "=r"(r[3]) : "r"(addr));
}
// silu on a packed f32x2, computed natively in bf16x2, returns bf16x2 word
static __device__ __forceinline__ uint32_t silu2bf(ull y2) {
    float2 yf = up2(y2);
    uint32_t yb, hb, tb, rb;
    asm("cvt.rn.bf16x2.f32 %0, %1, %2;" : "=r"(yb) : "f"(yf.y), "f"(yf.x));
    asm("mul.rn.bf16x2 %0, %1, %2;" : "=r"(hb) : "r"(yb), "r"(0x3F003F00u));
    asm("tanh.approx.bf16x2 %0, %1;" : "=r"(tb) : "r"(hb));
    asm("fma.rn.bf16x2 %0, %1, %2, %3;" : "=r"(rb) : "r"(hb), "r"(tb), "r"(hb));
    return rb;
}
static __device__ __forceinline__ uint32_t s2u(const void* p) {
    return (uint32_t)__cvta_generic_to_shared(p);
}
static __device__ __forceinline__ void cpa16(uint32_t dst, const void* src) {
    asm volatile("cp.async.ca.shared.global [%0], [%1], 16;" :: "r"(dst), "l"(src));
}

// ---------------------------------------------------------------------------
// hab: hA' = h @ W1[0:128] + b1 ; hB = h @ W1[128:256]; row sums to g_sA/g_sB.
// Also zeroes g_agg. W1 transposed on the fly (no prep kernel).
// ---------------------------------------------------------------------------
#define HAB_SMEM (17408 + 34816 + 1024)
__global__ void __launch_bounds__(256, 2)
hab_kernel(const float* __restrict__ h, const float* __restrict__ W1,
           const float* __restrict__ b1) {
    extern __shared__ unsigned char sm[];
    unsigned char* smA = sm;             // 64 x 272B
    unsigned char* smB = sm + 17408;     // 128 x 272B
    __nv_bfloat16* Bh = (__nv_bfloat16*)smB;
    float* part = (float*)(sm + 52224);  // 64 x 4 floats

    const int tid = threadIdx.x;
    const int nt0 = blockIdx.x * 64;
    const int hb = blockIdx.y;

    // zero g_agg (independent of the GEMM below)
    {
        int bidlin = blockIdx.y * gridDim.x + blockIdx.x;
        int stride = gridDim.x * 2 * 256;
        for (int i = bidlin * 256 + tid; i < NNODES * 9; i += stride) g_agg[i] = 0.f;
    }

    for (int idx = tid; idx < 64 * 32; idx += 256) {
        int i = idx >> 5, kq = idx & 31;
        float4 v = make_float4(0.f, 0.f, 0.f, 0.f);
        if (nt0 + i < NNODES) v = *(const float4*)(h + (size_t)(nt0 + i) * 128 + kq * 4);
        *(uint2*)(smA + i * 272 + kq * 8) = make_uint2(packbf(v.x, v.y), packbf(v.z, v.w));
    }
    // W1 rows hb*128..+127 transposed into smB: Bh[n*136 + k] = W1[hb*128+k][n]
    for (int idx = tid; idx < 128 * 128; idx += 256) {
        int k = idx >> 7, n = idx & 127;
        Bh[n * 136 + k] = __float2bfloat16(W1[(size_t)(hb * 128 + k) * 128 + n]);
    }
    __syncthreads();

    const int warp = tid >> 5, lane = tid & 31;
    const int lr = lane & 7, sel = lane >> 3, g = lane >> 2, t = lane & 3;
    const int R0 = (warp & 1) * 32, wc = warp >> 1, C0 = wc * 32;

    uint32_t aAddr[2], bAddr[2];
#pragma unroll
    for (int mt = 0; mt < 2; mt++)
        aAddr[mt] = s2u(smA + (R0 + 16 * mt + lr + (sel & 1) * 8) * 272 + (sel >> 1) * 16);
#pragma unroll
    for (int np = 0; np < 2; np++)
        bAddr[np] = s2u(smB + (C0 + 16 * np + lr + (sel >> 1) * 8) * 272 + (sel & 1) * 16);

    float acc[2][4][4];
#pragma unroll
    for (int mt = 0; mt < 2; mt++)
#pragma unroll
        for (int nt = 0; nt < 4; nt++)
#pragma unroll
            for (int u = 0; u < 4; u++) acc[mt][nt][u] = 0.f;

#pragma unroll
    for (int kb = 0; kb < 8; kb++) {
        uint32_t a[2][4], b[2][4];
        ldsm4(a[0], aAddr[0] + kb * 32);
        ldsm4(a[1], aAddr[1] + kb * 32);
        ldsm4(b[0], bAddr[0] + kb * 32);
        ldsm4(b[1], bAddr[1] + kb * 32);
#pragma unroll
        for (int mt = 0; mt < 2; mt++)
#pragma unroll
            for (int np = 0; np < 2; np++) {
                mma16816(acc[mt][2 * np], a[mt], &b[np][0]);
                mma16816(acc[mt][2 * np + 1], a[mt], &b[np][2]);
            }
    }

    float b1v[8];
#pragma unroll
    for (int nt = 0; nt < 4; nt++) {
        b1v[2 * nt] = (hb == 0) ? b1[C0 + 8 * nt + 2 * t] : 0.f;
        b1v[2 * nt + 1] = (hb == 0) ? b1[C0 + 8 * nt + 2 * t + 1] : 0.f;
    }

    float ps[4] = {0.f, 0.f, 0.f, 0.f};
    uint32_t* outw = (uint32_t*)g_hAB;
#pragma unroll
    for (int mt = 0; mt < 2; mt++)
#pragma unroll
        for (int nt = 0; nt < 4; nt++) {
            float v0 = acc[mt][nt][0] + b1v[2 * nt];
            float v1 = acc[mt][nt][1] + b1v[2 * nt + 1];
            float v2 = acc[mt][nt][2] + b1v[2 * nt];
            float v3 = acc[mt][nt][3] + b1v[2 * nt + 1];
            ps[2 * mt] += v0 + v1;
            ps[2 * mt + 1] += v2 + v3;
            int node0 = nt0 + R0 + 16 * mt + g;
            int cc = C0 + 8 * nt + 2 * t;
            if (node0 < NNODES)
                outw[((size_t)node0 * 256 + (hb << 7) + cc) >> 1] = packbf(v0, v1);
            if (node0 + 8 < NNODES)
                outw[((size_t)(node0 + 8) * 256 + (hb << 7) + cc) >> 1] = packbf(v2, v3);
        }
#pragma unroll
    for (int rl = 0; rl < 4; rl++) {
        ps[rl] += __shfl_xor_sync(0xffffffffu, ps[rl], 1);
        ps[rl] += __shfl_xor_sync(0xffffffffu, ps[rl], 2);
    }
    if (t == 0) {
#pragma unroll
        for (int rl = 0; rl < 4; rl++) {
            int row = R0 + 16 * (rl >> 1) + 8 * (rl & 1) + g;
            part[row * 4 + wc] = ps[rl];
        }
    }
    __syncthreads();
    if (tid < 64) {
        int node = nt0 + tid;
        if (node < NNODES) {
            float s = part[tid * 4] + part[tid * 4 + 1] + part[tid * 4 + 2] + part[tid * 4 + 3];
            if (hb == 0) g_sA[node] = s; else g_sB[node] = s;
        }
    }
}

// ---------------------------------------------------------------------------
// edge kernel (occ 3): 3-barrier pipeline, register GEMM2, bf16x2 silu,
// cp.async index prefetch + full-depth Stage A preload
// ---------------------------------------------------------------------------
#define OFF_XA   0                 // 64 x 272B  (X1 only)
#define OFF_W2   17408             // 128 x 272B
#define OFF_W3   52224             // 16 x 272B
#define OFF_P3   56576             // 4 x 64 x 40B  X3 bf16 partials per warp-col
#define OFF_PART 66816             // 64 x 8 f32 (LN2 stats partials)
#define OFF_PAR  68864             // params (3648B)
#define OFF_IDX  72512             // 8 warps x 96B prefetched indices
#define EDGE_SMEM 73280

__global__ void __launch_bounds__(256, 3)
edge_kernel(const float* __restrict__ W1, const float* __restrict__ g1,
            const float* __restrict__ be1,
            const float* __restrict__ W2, const float* __restrict__ b2,
            const float* __restrict__ g2, const float* __restrict__ be2,
            const float* __restrict__ W3,
            const int* __restrict__ rowI, const int* __restrict__ colI,
            const float* __restrict__ edge_attr, const float* __restrict__ edge_mask,
            const float* __restrict__ coord_diff) {
    extern __shared__ unsigned char sm[];
    unsigned char* smXA = sm + OFF_XA;
    uint32_t* XAw = (uint32_t*)smXA;
    __nv_bfloat16* W2h = (__nv_bfloat16*)(sm + OFF_W2);
    __nv_bfloat16* W3h = (__nv_bfloat16*)(sm + OFF_W3);
    uint32_t* P3w = (uint32_t*)(sm + OFF_P3);          // [wc][row][10 words]
    float* partp = (float*)(sm + OFF_PART);
    float* par = (float*)(sm + OFF_PAR);
    float* sw1c = par;           float* sg1 = par + 128;  float* sbe1 = par + 256;
    float* sb2 = par + 384;      float* sg2 = par + 512;  float* sbe2 = par + 640;
    float* sSw = par + 768;

    const int tid = threadIdx.x;
    if (tid < 128) {
        sw1c[tid] = W1[256 * 128 + tid];
        sg1[tid] = g1[tid]; sbe1[tid] = be1[tid];
        sb2[tid] = b2[tid]; sg2[tid] = g2[tid]; sbe2[tid] = be2[tid];
    }
    for (int idx = tid; idx < 128 * 128; idx += 256) {
        int k = idx >> 7, n = idx & 127;
        W2h[n * 136 + k] = __float2bfloat16(W2[idx]);
    }
    for (int idx = tid; idx < 16 * 128; idx += 256) {
        int n = idx >> 7, k = idx & 127;
        W3h[n * 136 + k] = __float2bfloat16(n < 9 ? W3[k * 9 + n] : 0.f);
    }
    __syncthreads();

    const int warp = tid >> 5, lane = tid & 31;
    const int lr = lane & 7, sel = lane >> 3, g = lane >> 2, t = lane & 3;
    const int R0 = (warp & 1) * 32, wc = warp >> 1, C0 = wc * 32;
    const int j0 = lane * 4;

    if (warp == 0) {
        float s = sw1c[lane] + sw1c[lane + 32] + sw1c[lane + 64] + sw1c[lane + 96];
#pragma unroll
        for (int o = 16; o > 0; o >>= 1) s += __shfl_xor_sync(0xffffffffu, s, o);
        if (lane == 0) sSw[0] = s;
    }
    __syncthreads();

    // packed per-lane LN1 parameters
    const ull w01  = *(const ull*)&sw1c[j0],  w23  = *(const ull*)&sw1c[j0 + 2];
    const ull g01  = *(const ull*)&sg1[j0],   g23  = *(const ull*)&sg1[j0 + 2];
    const ull be01 = *(const ull*)&sbe1[j0],  be23 = *(const ull*)&sbe1[j0 + 2];
    const float Sw = sSw[0];

    // ldmatrix base addresses
    uint32_t aAddr[2], bAddr[2];
#pragma unroll
    for (int mt = 0; mt < 2; mt++)
        aAddr[mt] = s2u(smXA + (R0 + 16 * mt + lr + (sel & 1) * 8) * 272 + (sel >> 1) * 16);
#pragma unroll
    for (int np = 0; np < 2; np++)
        bAddr[np] = s2u(sm + OFF_W2 + (C0 + 16 * np + lr + (sel >> 1) * 8) * 272 + (sel & 1) * 16);
    const uint32_t bAddr3 = s2u(sm + OFF_W3 + (lr + (sel >> 1) * 8) * 272 + (sel & 1) * 16) + wc * 64;

    const uint32_t idxDst = s2u(sm + OFF_IDX) + warp * 96;
    const int* idxR = (const int*)(sm + OFF_IDX + warp * 96);
    const int* idxC = idxR + 8;
    const float* idxE = (const float*)(idxR + 16);

    // prefetch indices for the first tile
    {
        int en0 = blockIdx.x * MTILE + warp * 8;
        if (lane < 6) {
            int seg = lane >> 1, half = lane & 1;
            const char* src = seg == 0 ? (const char*)(rowI + en0)
                            : seg == 1 ? (const char*)(colI + en0)
                                       : (const char*)(edge_attr + en0);
            cpa16(idxDst + seg * 32 + half * 16, src + half * 16);
        }
        asm volatile("cp.async.commit_group;" ::: "memory");
    }

    for (int tile = blockIdx.x; tile < NTILES; tile += EDGE_GRID) {
        const int ebase = tile * MTILE;

        // ---- Stage A: idx from smem, full-depth gather preload, LN1+SiLU ----
        asm volatile("cp.async.wait_group 0;" ::: "memory");
        __syncwarp();
        int rs8[8], cs8[8]; float eas[8];
#pragma unroll
        for (int it = 0; it < 8; it++) {
            rs8[it] = idxR[it]; cs8[it] = idxC[it]; eas[it] = idxE[it];
        }
        uint2 pwa[8], pwb[8]; float psa[8], psb[8];
#pragma unroll
        for (int it = 0; it < 8; it++) {
            pwa[it] = *(const uint2*)(g_hAB + (size_t)rs8[it] * 256 + j0);
            pwb[it] = *(const uint2*)(g_hAB + (size_t)cs8[it] * 256 + 128 + j0);
            psa[it] = __ldg(g_sA + rs8[it]);
            psb[it] = __ldg(g_sB + cs8[it]);
        }
#pragma unroll
        for (int it = 0; it < 8; it++) {
            float ea = eas[it];
            ull a01 = bf2f2(pwa[it].x), a23 = bf2f2(pwa[it].y);
            ull f01 = bf2f2(pwb[it].x), f23 = bf2f2(pwb[it].y);
            ull ea2 = pk2(ea, ea);
            ull x01 = fma2(ea2, w01, add2(a01, f01));
            ull x23 = fma2(ea2, w23, add2(a23, f23));
            ull q2 = fma2(x01, x01, mul2(x23, x23));
            float2 qf = up2(q2);
            float q = qf.x + qf.y;
#pragma unroll
            for (int o = 16; o > 0; o >>= 1) q += __shfl_xor_sync(0xffffffffu, q, o);
            float mean = (psa[it] + psb[it] + ea * Sw) * (1.f / 128.f);
            float var = q * (1.f / 128.f) - mean * mean;
            float rsv = rsqrtf(var + 1e-5f);
            float mrs = -mean * rsv;
            ull rsv2 = pk2(rsv, rsv), mrs2 = pk2(mrs, mrs);
            ull y01 = fma2(fma2(x01, rsv2, mrs2), g01, be01);
            ull y23 = fma2(fma2(x23, rsv2, mrs2), g23, be23);
            *(uint2*)&XAw[(warp * 8 + it) * 68 + lane * 2] =
                make_uint2(silu2bf(y01), silu2bf(y23));
        }
        __syncthreads();   // sync1: X1 ready

        // ---- GEMM1: acc = X1 @ W2 ----
        float acc[2][4][4];
#pragma unroll
        for (int mt = 0; mt < 2; mt++)
#pragma unroll
            for (int nt = 0; nt < 4; nt++)
#pragma unroll
                for (int u = 0; u < 4; u++) acc[mt][nt][u] = 0.f;
#pragma unroll
        for (int kb = 0; kb < 8; kb++) {
            uint32_t a[2][4], b[2][4];
            ldsm4(a[0], aAddr[0] + kb * 32);
            ldsm4(a[1], aAddr[1] + kb * 32);
            ldsm4(b[0], bAddr[0] + kb * 32);
            ldsm4(b[1], bAddr[1] + kb * 32);
#pragma unroll
            for (int mt = 0; mt < 2; mt++)
#pragma unroll
                for (int np = 0; np < 2; np++) {
                    mma16816(acc[mt][2 * np], a[mt], &b[np][0]);
                    mma16816(acc[mt][2 * np + 1], a[mt], &b[np][2]);
                }
        }
        // bias + per-row partial sums (for LN2), packed f32x2
        ull accp[2][4][2];
        ull psA[4], pqA[4];
#pragma unroll
        for (int rl = 0; rl < 4; rl++) { psA[rl] = 0ull; pqA[rl] = 0ull; }
#pragma unroll
        for (int mt = 0; mt < 2; mt++)
#pragma unroll
            for (int nt = 0; nt < 4; nt++) {
                ull bb = *(const ull*)&sb2[C0 + 8 * nt + 2 * t];
                ull v01 = add2(pk2(acc[mt][nt][0], acc[mt][nt][1]), bb);
                ull v23 = add2(pk2(acc[mt][nt][2], acc[mt][nt][3]), bb);
                accp[mt][nt][0] = v01; accp[mt][nt][1] = v23;
                psA[2 * mt] = add2(psA[2 * mt], v01);
                pqA[2 * mt] = fma2(v01, v01, pqA[2 * mt]);
                psA[2 * mt + 1] = add2(psA[2 * mt + 1], v23);
                pqA[2 * mt + 1] = fma2(v23, v23, pqA[2 * mt + 1]);
            }
        float ps[4], pq[4];
#pragma unroll
        for (int rl = 0; rl < 4; rl++) {
            float2 pf = up2(psA[rl]); ps[rl] = pf.x + pf.y;
            float2 qf = up2(pqA[rl]); pq[rl] = qf.x + qf.y;
            ps[rl] += __shfl_xor_sync(0xffffffffu, ps[rl], 1);
            ps[rl] += __shfl_xor_sync(0xffffffffu, ps[rl], 2);
            pq[rl] += __shfl_xor_sync(0xffffffffu, pq[rl], 1);
            pq[rl] += __shfl_xor_sync(0xffffffffu, pq[rl], 2);
        }
        if (t == 0) {
#pragma unroll
            for (int rl = 0; rl < 4; rl++) {
                int row = R0 + 16 * (rl >> 1) + 8 * (rl & 1) + g;
                *(float2*)&partp[row * 8 + wc * 2] = make_float2(ps[rl], pq[rl]);
            }
        }
        __syncthreads();   // sync2: stats partials ready

        // ---- LN2 + SiLU in registers -> A-fragments ypk (bf16x2) ----
        ull rs2[4], mr2[4];
#pragma unroll
        for (int rl = 0; rl < 4; rl++) {
            int row = R0 + 16 * (rl >> 1) + 8 * (rl & 1) + g;
            float4 pA = *(const float4*)&partp[row * 8];
            float4 pB = *(const float4*)&partp[row * 8 + 4];
            float s = pA.x + pA.z + pB.x + pB.z;
            float q = pA.y + pA.w + pB.y + pB.w;
            float mean = s * (1.f / 128.f);
            float var = q * (1.f / 128.f) - mean * mean;
            float rsv = rsqrtf(var + 1e-5f);
            float mrs = -mean * rsv;
            rs2[rl] = pk2(rsv, rsv);
            mr2[rl] = pk2(mrs, mrs);
        }
        uint32_t ypk[2][4][2];
#pragma unroll
        for (int mt = 0; mt < 2; mt++)
#pragma unroll
            for (int nt = 0; nt < 4; nt++) {
                int rl0 = 2 * mt, rl1 = 2 * mt + 1;
                ull gg = *(const ull*)&sg2[C0 + 8 * nt + 2 * t];
                ull ee = *(const ull*)&sbe2[C0 + 8 * nt + 2 * t];
                ull y01 = fma2(fma2(accp[mt][nt][0], rs2[rl0], mr2[rl0]), gg, ee);
                ull y23 = fma2(fma2(accp[mt][nt][1], rs2[rl1], mr2[rl1]), gg, ee);
                ypk[mt][nt][0] = silu2bf(y01);
                ypk[mt][nt][1] = silu2bf(y23);
            }

        // ---- GEMM2 from registers: partial X3 for this warp's K-slice ----
        float a3[2][2][4];
#pragma unroll
        for (int mt = 0; mt < 2; mt++)
#pragma unroll
            for (int nb = 0; nb < 2; nb++)
#pragma unroll
                for (int u = 0; u < 4; u++) a3[mt][nb][u] = 0.f;
#pragma unroll
        for (int kb2 = 0; kb2 < 2; kb2++) {
            uint32_t bb[4];
            ldsm4(bb, bAddr3 + kb2 * 32);
#pragma unroll
            for (int mt = 0; mt < 2; mt++) {
                uint32_t af[4] = { ypk[mt][2 * kb2][0], ypk[mt][2 * kb2][1],
                                   ypk[mt][2 * kb2 + 1][0], ypk[mt][2 * kb2 + 1][1] };
                mma16816(a3[mt][0], af, &bb[0]);
                mma16816(a3[mt][1], af, &bb[2]);
            }
        }
        // store bf16 partials: buffer wc, row pitch 10 words
        {
            uint32_t* p3 = P3w + wc * 640;
#pragma unroll
            for (int mt = 0; mt < 2; mt++)
#pragma unroll
                for (int nb = 0; nb < 2; nb++) {
                    int row = R0 + 16 * mt + g;
                    int w = 4 * nb + t;
                    p3[row * 10 + w] = packbf(a3[mt][nb][0], a3[mt][nb][1]);
                    p3[(row + 8) * 10 + w] = packbf(a3[mt][nb][2], a3[mt][nb][3]);
                }
        }

        // ---- prefetch next tile's indices (cp.async, zero reg cost) ----
        {
            int tile_n = tile + EDGE_GRID;
            if (tile_n < NTILES && lane < 6) {
                int en0 = tile_n * MTILE + warp * 8;
                int seg = lane >> 1, half = lane & 1;
                const char* src = seg == 0 ? (const char*)(rowI + en0)
                                : seg == 1 ? (const char*)(colI + en0)
                                           : (const char*)(edge_attr + en0);
                cpa16(idxDst + seg * 32 + half * 16, src + half * 16);
            }
            asm volatile("cp.async.commit_group;" ::: "memory");
        }

        // ---- preload scatter operands so their latency overlaps sync3 ----
        float cd[9]; int r2 = 0; float em = 0.f;
        if (warp == 4 || warp == 5) {
            int el = tid - 128;
            int e2 = ebase + el;
            const float* cdp = coord_diff + (size_t)e2 * 9;
#pragma unroll
            for (int c9 = 0; c9 < 9; c9++) cd[c9] = __ldg(cdp + c9);
            r2 = __ldg(rowI + e2);
            em = __ldg(edge_mask + e2);
        }
        __syncthreads();   // sync3: X3 partials ready

        // ---- scatter (warps 4-5): sum partials, transform, atomics ----
        if (warp == 4 || warp == 5) {
            int el = tid - 128;
            float ph[10];
#pragma unroll
            for (int w = 0; w < 5; w++) {
                ull sacc = add2(add2(bf2f2(P3w[el * 10 + w]), bf2f2(P3w[640 + el * 10 + w])),
                                add2(bf2f2(P3w[1280 + el * 10 + w]), bf2f2(P3w[1920 + el * 10 + w])));
                float2 f = up2(sacc);
                ph[2 * w] = f.x; ph[2 * w + 1] = f.y;
            }
            float* aggp = g_agg + (size_t)r2 * 9;
#pragma unroll
            for (int l = 0; l < 3; l++)
#pragma unroll
                for (int k = 0; k < 3; k++) {
                    float tr = cd[k] * ph[l] + cd[3 + k] * ph[3 + l] + cd[6 + k] * ph[6 + l];
                    atomicAdd(aggp + l * 3 + k, tr * em);
                }
        }
    }
}

__global__ void finalize_kernel(const float* __restrict__ coord,
                                const float* __restrict__ node_mask,
                                float* __restrict__ out) {
    int i4 = blockIdx.x * 256 + threadIdx.x;
    if (i4 < (NNODES * 9) / 4) {     // 450000 = 112500 * 4 exactly
        float4 c = ((const float4*)coord)[i4];
        float4 a = ((const float4*)g_agg)[i4];
        int i = i4 * 4;
        float4 o;
        o.x = (c.x + a.x * 0.01f) * __ldg(node_mask + (i    ) / 9);
        o.y = (c.y + a.y * 0.01f) * __ldg(node_mask + (i + 1) / 9);
        o.z = (c.z + a.z * 0.01f) * __ldg(node_mask + (i + 2) / 9);
        o.w = (c.w + a.w * 0.01f) * __ldg(node_mask + (i + 3) / 9);
        ((float4*)out)[i4] = o;
    }
}

extern "C" void kernel_launch(void* const* d_in, const int* in_sizes, int n_in,
                              void* d_out, int out_size) {
    const float* h          = (const float*)d_in[0];
    const float* coord      = (const float*)d_in[1];
    const float* coord_diff = (const float*)d_in[2];
    const float* edge_attr  = (const float*)d_in[3];
    const float* edge_mask  = (const float*)d_in[4];
    const float* node_mask  = (const float*)d_in[5];
    const int*   rowI       = (const int*)d_in[6];
    const int*   colI       = (const int*)d_in[7];
    const float* W1  = (const float*)d_in[8];
    const float* b1  = (const float*)d_in[9];
    const float* g1  = (const float*)d_in[10];
    const float* be1 = (const float*)d_in[11];
    const float* W2  = (const float*)d_in[12];
    const float* b2  = (const float*)d_in[13];
    const float* g2  = (const float*)d_in[14];
    const float* be2 = (const float*)d_in[15];
    const float* W3  = (const float*)d_in[16];
    float* out = (float*)d_out;

    cudaFuncSetAttribute(hab_kernel, cudaFuncAttributeMaxDynamicSharedMemorySize, HAB_SMEM);
    cudaFuncSetAttribute(edge_kernel, cudaFuncAttributeMaxDynamicSharedMemorySize, EDGE_SMEM);

    hab_kernel<<<dim3((NNODES + 63) / 64, 2), 256, HAB_SMEM>>>(h, W1, b1);
    edge_kernel<<<EDGE_GRID, 256, EDGE_SMEM>>>(W1, g1, be1, W2, b2, g2, be2, W3,
                                               rowI, colI, edge_attr, edge_mask, coord_diff);
    finalize_kernel<<<((NNODES * 9) / 4 + 255) / 256, 256>>>(coord, node_mask, out);
}

// round 13
// speedup vs baseline: 1.0880x; 1.0880x over previous
#include <cuda_runtime.h>
#include <cuda_bf16.h>
#include <cuda_fp16.h>
#include <stdint.h>

#define NNODES 50000
#define NEDGES 800000
#define MTILE 64
#define NTILES (NEDGES / MTILE)   // 12500
#define EDGE_GRID 444

typedef unsigned long long ull;

// ---------------- scratch ----------------
__device__ __align__(128) __nv_bfloat16 g_hAB[(size_t)NNODES * 256];
__device__ __align__(128) __nv_bfloat16 g_W1T[2 * 128 * 128];
__device__ float g_sA[NNODES];
__device__ float g_sB[NNODES];
__device__ float g_agg[NNODES * 9];

// ---------------- helpers ----------------
static __device__ __forceinline__ uint32_t packbf(float a, float b) {
    __nv_bfloat162 h = __floats2bfloat162_rn(a, b);
    return *reinterpret_cast<uint32_t*>(&h);
}
// ---- packed f32x2 ----
static __device__ __forceinline__ ull pk2(float lo, float hi) {
    ull r; asm("mov.b64 %0, {%1, %2};" : "=l"(r) : "f"(lo), "f"(hi)); return r;
}
static __device__ __forceinline__ float2 up2(ull v) {
    float2 f; asm("mov.b64 {%0, %1}, %2;" : "=f"(f.x), "=f"(f.y) : "l"(v)); return f;
}
static __device__ __forceinline__ ull add2(ull a, ull b) {
    ull r; asm("add.rn.f32x2 %0, %1, %2;" : "=l"(r) : "l"(a), "l"(b)); return r;
}
static __device__ __forceinline__ ull mul2(ull a, ull b) {
    ull r; asm("mul.rn.f32x2 %0, %1, %2;" : "=l"(r) : "l"(a), "l"(b)); return r;
}
static __device__ __forceinline__ ull fma2(ull a, ull b, ull c) {
    ull r; asm("fma.rn.f32x2 %0, %1, %2, %3;" : "=l"(r) : "l"(a), "l"(b), "l"(c)); return r;
}
// bf16x2 word -> f32x2 (element order preserved)
static __device__ __forceinline__ ull bf2f2(uint32_t u) {
    uint32_t lo = u << 16;
    uint32_t hi = u & 0xFFFF0000u;
    ull r; asm("mov.b64 %0, {%1, %2};" : "=l"(r) : "r"(lo), "r"(hi)); return r;
}

static __device__ __forceinline__ void mma16816(float* c, const uint32_t* a, const uint32_t* b) {
    asm volatile(
        "mma.sync.aligned.m16n8k16.row.col.f32.bf16.bf16.f32 "
        "{%0,%1,%2,%3}, {%4,%5,%6,%7}, {%8,%9}, {%0,%1,%2,%3};\n"
        : "+f"(c[0]), "+f"(c[1]), "+f"(c[2]), "+f"(c[3])
        : "r"(a[0]), "r"(a[1]), "r"(a[2]), "r"(a[3]), "r"(b[0]), "r"(b[1]));
}
static __device__ __forceinline__ void ldsm4(uint32_t* r, uint32_t addr) {
    asm volatile("ldmatrix.sync.aligned.m8n8.x4.shared.b16 {%0,%1,%2,%3}, [%4];"
        : "=r"(r[0]), "=r"(r[1]), "=r"(r[2]), "=r"(r[3]) : "r"(addr));
}
// silu on a packed f32x2, computed natively in bf16x2, returns bf16x2 word
static __device__ __forceinline__ uint32_t silu2bf(ull y2) {
    float2 yf = up2(y2);
    uint32_t yb, hb, tb, rb;
    asm("cvt.rn.bf16x2.f32 %0, %1, %2;" : "=r"(yb) : "f"(yf.y), "f"(yf.x));
    asm("mul.rn.bf16x2 %0, %1, %2;" : "=r"(hb) : "r"(yb), "r"(0x3F003F00u));
    asm("tanh.approx.bf16x2 %0, %1;" : "=r"(tb) : "r"(hb));
    asm("fma.rn.bf16x2 %0, %1, %2, %3;" : "=r"(rb) : "r"(hb), "r"(tb), "r"(hb));
    return rb;
}
static __device__ __forceinline__ uint32_t s2u(const void* p) {
    return (uint32_t)__cvta_generic_to_shared(p);
}
static __device__ __forceinline__ void cpa16(uint32_t dst, const void* src) {
    asm volatile("cp.async.ca.shared.global [%0], [%1], 16;" :: "r"(dst), "l"(src));
}

// ---------------------------------------------------------------------------
// prep: W1 -> bf16 transposed halves (coalesced writes); zero agg
// ---------------------------------------------------------------------------
__global__ void prep_kernel(const float* __restrict__ W1) {
    int i = blockIdx.x * 256 + threadIdx.x;
    if (i < 2 * 128 * 128) {
        int hb = i >> 14, n = (i >> 7) & 127, k = i & 127;
        g_W1T[i] = __float2bfloat16(W1[(size_t)(hb * 128 + k) * 128 + n]);
    }
    if (i < NNODES * 9) g_agg[i] = 0.f;
}

// ---------------------------------------------------------------------------
// hab: both halves in one block. hA' = h@W1[0:128]+b1 ; hB = h@W1[128:256];
// row sums to g_sA/g_sB. grid 782, block 256, occ 2.
// ---------------------------------------------------------------------------
#define HAB_SMEM (17408 + 2 * 34816 + 2048)   // 89856
__global__ void __launch_bounds__(256, 2)
hab_kernel(const float* __restrict__ h, const float* __restrict__ b1) {
    extern __shared__ unsigned char sm[];
    unsigned char* smA = sm;                    // 64 x 272B
    unsigned char* smB = sm + 17408;            // 2 x (128 x 272B)
    float* part = (float*)(sm + 17408 + 2 * 34816);  // 2 x (64 x 4) floats

    const int tid = threadIdx.x;
    const int nt0 = blockIdx.x * 64;

    for (int idx = tid; idx < 64 * 32; idx += 256) {
        int i = idx >> 5, kq = idx & 31;
        float4 v = make_float4(0.f, 0.f, 0.f, 0.f);
        if (nt0 + i < NNODES) v = *(const float4*)(h + (size_t)(nt0 + i) * 128 + kq * 4);
        *(uint2*)(smA + i * 272 + kq * 8) = make_uint2(packbf(v.x, v.y), packbf(v.z, v.w));
    }
    // both W1T halves, uint4 coalesced
    for (int idx = tid; idx < 2 * 128 * 16; idx += 256) {
        int hb = idx >> 11, rem = idx & 2047;
        int n = rem >> 4, q = rem & 15;
        *(uint4*)(smB + hb * 34816 + n * 272 + q * 16) =
            ((const uint4*)(g_W1T + (hb << 14)))[rem];
    }
    __syncthreads();

    const int warp = tid >> 5, lane = tid & 31;
    const int lr = lane & 7, sel = lane >> 3, g = lane >> 2, t = lane & 3;
    const int R0 = (warp & 1) * 32, wc = warp >> 1, C0 = wc * 32;

    uint32_t aAddr[2], bAddr[2];
#pragma unroll
    for (int mt = 0; mt < 2; mt++)
        aAddr[mt] = s2u(smA + (R0 + 16 * mt + lr + (sel & 1) * 8) * 272 + (sel >> 1) * 16);
#pragma unroll
    for (int np = 0; np < 2; np++)
        bAddr[np] = s2u(smB + (C0 + 16 * np + lr + (sel >> 1) * 8) * 272 + (sel & 1) * 16);

    uint32_t* outw = (uint32_t*)g_hAB;
#pragma unroll
    for (int hb = 0; hb < 2; hb++) {
        float acc[2][4][4];
#pragma unroll
        for (int mt = 0; mt < 2; mt++)
#pragma unroll
            for (int nt = 0; nt < 4; nt++)
#pragma unroll
                for (int u = 0; u < 4; u++) acc[mt][nt][u] = 0.f;

#pragma unroll
        for (int kb = 0; kb < 8; kb++) {
            uint32_t a[2][4], b[2][4];
            ldsm4(a[0], aAddr[0] + kb * 32);
            ldsm4(a[1], aAddr[1] + kb * 32);
            ldsm4(b[0], bAddr[0] + hb * 34816 + kb * 32);
            ldsm4(b[1], bAddr[1] + hb * 34816 + kb * 32);
#pragma unroll
            for (int mt = 0; mt < 2; mt++)
#pragma unroll
                for (int np = 0; np < 2; np++) {
                    mma16816(acc[mt][2 * np], a[mt], &b[np][0]);
                    mma16816(acc[mt][2 * np + 1], a[mt], &b[np][2]);
                }
        }

        float b1v[8];
#pragma unroll
        for (int nt = 0; nt < 4; nt++) {
            b1v[2 * nt] = (hb == 0) ? b1[C0 + 8 * nt + 2 * t] : 0.f;
            b1v[2 * nt + 1] = (hb == 0) ? b1[C0 + 8 * nt + 2 * t + 1] : 0.f;
        }

        float ps[4] = {0.f, 0.f, 0.f, 0.f};
#pragma unroll
        for (int mt = 0; mt < 2; mt++)
#pragma unroll
            for (int nt = 0; nt < 4; nt++) {
                float v0 = acc[mt][nt][0] + b1v[2 * nt];
                float v1 = acc[mt][nt][1] + b1v[2 * nt + 1];
                float v2 = acc[mt][nt][2] + b1v[2 * nt];
                float v3 = acc[mt][nt][3] + b1v[2 * nt + 1];
                ps[2 * mt] += v0 + v1;
                ps[2 * mt + 1] += v2 + v3;
                int node0 = nt0 + R0 + 16 * mt + g;
                int cc = C0 + 8 * nt + 2 * t;
                if (node0 < NNODES)
                    outw[((size_t)node0 * 256 + (hb << 7) + cc) >> 1] = packbf(v0, v1);
                if (node0 + 8 < NNODES)
                    outw[((size_t)(node0 + 8) * 256 + (hb << 7) + cc) >> 1] = packbf(v2, v3);
            }
#pragma unroll
        for (int rl = 0; rl < 4; rl++) {
            ps[rl] += __shfl_xor_sync(0xffffffffu, ps[rl], 1);
            ps[rl] += __shfl_xor_sync(0xffffffffu, ps[rl], 2);
        }
        if (t == 0) {
#pragma unroll
            for (int rl = 0; rl < 4; rl++) {
                int row = R0 + 16 * (rl >> 1) + 8 * (rl & 1) + g;
                part[hb * 256 + row * 4 + wc] = ps[rl];
            }
        }
    }
    __syncthreads();
    if (tid < 64) {
        int node = nt0 + tid;
        if (node < NNODES) {
            g_sA[node] = part[tid * 4] + part[tid * 4 + 1] + part[tid * 4 + 2] + part[tid * 4 + 3];
            g_sB[node] = part[256 + tid * 4] + part[256 + tid * 4 + 1]
                       + part[256 + tid * 4 + 2] + part[256 + tid * 4 + 3];
        }
    }
}

// ---------------------------------------------------------------------------
// edge kernel (occ 3): 3-barrier pipeline, register GEMM2, bf16x2 silu,
// cp.async index prefetch + full-depth Stage A preload
// ---------------------------------------------------------------------------
#define OFF_XA   0                 // 64 x 272B  (X1 only)
#define OFF_W2   17408             // 128 x 272B
#define OFF_W3   52224             // 16 x 272B
#define OFF_P3   56576             // 4 x 64 x 40B  X3 bf16 partials per warp-col
#define OFF_PART 66816             // 64 x 8 f32 (LN2 stats partials)
#define OFF_PAR  68864             // params (3648B)
#define OFF_IDX  72512             // 8 warps x 96B prefetched indices
#define EDGE_SMEM 73280

__global__ void __launch_bounds__(256, 3)
edge_kernel(const float* __restrict__ W1, const float* __restrict__ g1,
            const float* __restrict__ be1,
            const float* __restrict__ W2, const float* __restrict__ b2,
            const float* __restrict__ g2, const float* __restrict__ be2,
            const float* __restrict__ W3,
            const int* __restrict__ rowI, const int* __restrict__ colI,
            const float* __restrict__ edge_attr, const float* __restrict__ edge_mask,
            const float* __restrict__ coord_diff) {
    extern __shared__ unsigned char sm[];
    unsigned char* smXA = sm + OFF_XA;
    uint32_t* XAw = (uint32_t*)smXA;
    __nv_bfloat16* W2h = (__nv_bfloat16*)(sm + OFF_W2);
    __nv_bfloat16* W3h = (__nv_bfloat16*)(sm + OFF_W3);
    uint32_t* P3w = (uint32_t*)(sm + OFF_P3);          // [wc][row][10 words]
    float* partp = (float*)(sm + OFF_PART);
    float* par = (float*)(sm + OFF_PAR);
    float* sw1c = par;           float* sg1 = par + 128;  float* sbe1 = par + 256;
    float* sb2 = par + 384;      float* sg2 = par + 512;  float* sbe2 = par + 640;
    float* sSw = par + 768;

    const int tid = threadIdx.x;
    if (tid < 128) {
        sw1c[tid] = W1[256 * 128 + tid];
        sg1[tid] = g1[tid]; sbe1[tid] = be1[tid];
        sb2[tid] = b2[tid]; sg2[tid] = g2[tid]; sbe2[tid] = be2[tid];
    }
    for (int idx = tid; idx < 128 * 128; idx += 256) {
        int k = idx >> 7, n = idx & 127;
        W2h[n * 136 + k] = __float2bfloat16(W2[idx]);
    }
    for (int idx = tid; idx < 16 * 128; idx += 256) {
        int n = idx >> 7, k = idx & 127;
        W3h[n * 136 + k] = __float2bfloat16(n < 9 ? W3[k * 9 + n] : 0.f);
    }
    __syncthreads();

    const int warp = tid >> 5, lane = tid & 31;
    const int lr = lane & 7, sel = lane >> 3, g = lane >> 2, t = lane & 3;
    const int R0 = (warp & 1) * 32, wc = warp >> 1, C0 = wc * 32;
    const int j0 = lane * 4;

    if (warp == 0) {
        float s = sw1c[lane] + sw1c[lane + 32] + sw1c[lane + 64] + sw1c[lane + 96];
#pragma unroll
        for (int o = 16; o > 0; o >>= 1) s += __shfl_xor_sync(0xffffffffu, s, o);
        if (lane == 0) sSw[0] = s;
    }
    __syncthreads();

    // packed per-lane LN1 parameters
    const ull w01  = *(const ull*)&sw1c[j0],  w23  = *(const ull*)&sw1c[j0 + 2];
    const ull g01  = *(const ull*)&sg1[j0],   g23  = *(const ull*)&sg1[j0 + 2];
    const ull be01 = *(const ull*)&sbe1[j0],  be23 = *(const ull*)&sbe1[j0 + 2];
    const float Sw = sSw[0];

    // ldmatrix base addresses
    uint32_t aAddr[2], bAddr[2];
#pragma unroll
    for (int mt = 0; mt < 2; mt++)
        aAddr[mt] = s2u(smXA + (R0 + 16 * mt + lr + (sel & 1) * 8) * 272 + (sel >> 1) * 16);
#pragma unroll
    for (int np = 0; np < 2; np++)
        bAddr[np] = s2u(sm + OFF_W2 + (C0 + 16 * np + lr + (sel >> 1) * 8) * 272 + (sel & 1) * 16);
    const uint32_t bAddr3 = s2u(sm + OFF_W3 + (lr + (sel >> 1) * 8) * 272 + (sel & 1) * 16) + wc * 64;

    const uint32_t idxDst = s2u(sm + OFF_IDX) + warp * 96;
    const int* idxR = (const int*)(sm + OFF_IDX + warp * 96);
    const int* idxC = idxR + 8;
    const float* idxE = (const float*)(idxR + 16);

    // prefetch indices for the first tile
    {
        int en0 = blockIdx.x * MTILE + warp * 8;
        if (lane < 6) {
            int seg = lane >> 1, half = lane & 1;
            const char* src = seg == 0 ? (const char*)(rowI + en0)
                            : seg == 1 ? (const char*)(colI + en0)
                                       : (const char*)(edge_attr + en0);
            cpa16(idxDst + seg * 32 + half * 16, src + half * 16);
        }
        asm volatile("cp.async.commit_group;" ::: "memory");
    }

    for (int tile = blockIdx.x; tile < NTILES; tile += EDGE_GRID) {
        const int ebase = tile * MTILE;

        // ---- Stage A: idx from smem, full-depth gather preload, LN1+SiLU ----
        asm volatile("cp.async.wait_group 0;" ::: "memory");
        __syncwarp();
        int rs8[8], cs8[8]; float eas[8];
#pragma unroll
        for (int it = 0; it < 8; it++) {
            rs8[it] = idxR[it]; cs8[it] = idxC[it]; eas[it] = idxE[it];
        }
        uint2 pwa[8], pwb[8]; float psa[8], psb[8];
#pragma unroll
        for (int it = 0; it < 8; it++) {
            pwa[it] = *(const uint2*)(g_hAB + (size_t)rs8[it] * 256 + j0);
            pwb[it] = *(const uint2*)(g_hAB + (size_t)cs8[it] * 256 + 128 + j0);
            psa[it] = __ldg(g_sA + rs8[it]);
            psb[it] = __ldg(g_sB + cs8[it]);
        }
#pragma unroll
        for (int it = 0; it < 8; it++) {
            float ea = eas[it];
            ull a01 = bf2f2(pwa[it].x), a23 = bf2f2(pwa[it].y);
            ull f01 = bf2f2(pwb[it].x), f23 = bf2f2(pwb[it].y);
            ull ea2 = pk2(ea, ea);
            ull x01 = fma2(ea2, w01, add2(a01, f01));
            ull x23 = fma2(ea2, w23, add2(a23, f23));
            ull q2 = fma2(x01, x01, mul2(x23, x23));
            float2 qf = up2(q2);
            float q = qf.x + qf.y;
#pragma unroll
            for (int o = 16; o > 0; o >>= 1) q += __shfl_xor_sync(0xffffffffu, q, o);
            float mean = (psa[it] + psb[it] + ea * Sw) * (1.f / 128.f);
            float var = q * (1.f / 128.f) - mean * mean;
            float rsv = rsqrtf(var + 1e-5f);
            float mrs = -mean * rsv;
            ull rsv2 = pk2(rsv, rsv), mrs2 = pk2(mrs, mrs);
            ull y01 = fma2(fma2(x01, rsv2, mrs2), g01, be01);
            ull y23 = fma2(fma2(x23, rsv2, mrs2), g23, be23);
            *(uint2*)&XAw[(warp * 8 + it) * 68 + lane * 2] =
                make_uint2(silu2bf(y01), silu2bf(y23));
        }
        __syncthreads();   // sync1: X1 ready

        // ---- GEMM1: acc = X1 @ W2 ----
        float acc[2][4][4];
#pragma unroll
        for (int mt = 0; mt < 2; mt++)
#pragma unroll
            for (int nt = 0; nt < 4; nt++)
#pragma unroll
                for (int u = 0; u < 4; u++) acc[mt][nt][u] = 0.f;
#pragma unroll
        for (int kb = 0; kb < 8; kb++) {
            uint32_t a[2][4], b[2][4];
            ldsm4(a[0], aAddr[0] + kb * 32);
            ldsm4(a[1], aAddr[1] + kb * 32);
            ldsm4(b[0], bAddr[0] + kb * 32);
            ldsm4(b[1], bAddr[1] + kb * 32);
#pragma unroll
            for (int mt = 0; mt < 2; mt++)
#pragma unroll
                for (int np = 0; np < 2; np++) {
                    mma16816(acc[mt][2 * np], a[mt], &b[np][0]);
                    mma16816(acc[mt][2 * np + 1], a[mt], &b[np][2]);
                }
        }
        // bias + per-row partial sums (for LN2), packed f32x2
        ull accp[2][4][2];
        ull psA[4], pqA[4];
#pragma unroll
        for (int rl = 0; rl < 4; rl++) { psA[rl] = 0ull; pqA[rl] = 0ull; }
#pragma unroll
        for (int mt = 0; mt < 2; mt++)
#pragma unroll
            for (int nt = 0; nt < 4; nt++) {
                ull bb = *(const ull*)&sb2[C0 + 8 * nt + 2 * t];
                ull v01 = add2(pk2(acc[mt][nt][0], acc[mt][nt][1]), bb);
                ull v23 = add2(pk2(acc[mt][nt][2], acc[mt][nt][3]), bb);
                accp[mt][nt][0] = v01; accp[mt][nt][1] = v23;
                psA[2 * mt] = add2(psA[2 * mt], v01);
                pqA[2 * mt] = fma2(v01, v01, pqA[2 * mt]);
                psA[2 * mt + 1] = add2(psA[2 * mt + 1], v23);
                pqA[2 * mt + 1] = fma2(v23, v23, pqA[2 * mt + 1]);
            }
        float ps[4], pq[4];
#pragma unroll
        for (int rl = 0; rl < 4; rl++) {
            float2 pf = up2(psA[rl]); ps[rl] = pf.x + pf.y;
            float2 qf = up2(pqA[rl]); pq[rl] = qf.x + qf.y;
            ps[rl] += __shfl_xor_sync(0xffffffffu, ps[rl], 1);
            ps[rl] += __shfl_xor_sync(0xffffffffu, ps[rl], 2);
            pq[rl] += __shfl_xor_sync(0xffffffffu, pq[rl], 1);
            pq[rl] += __shfl_xor_sync(0xffffffffu, pq[rl], 2);
        }
        if (t == 0) {
#pragma unroll
            for (int rl = 0; rl < 4; rl++) {
                int row = R0 + 16 * (rl >> 1) + 8 * (rl & 1) + g;
                *(float2*)&partp[row * 8 + wc * 2] = make_float2(ps[rl], pq[rl]);
            }
        }
        __syncthreads();   // sync2: stats partials ready

        // ---- LN2 + SiLU in registers -> A-fragments ypk (bf16x2) ----
        ull rs2[4], mr2[4];
#pragma unroll
        for (int rl = 0; rl < 4; rl++) {
            int row = R0 + 16 * (rl >> 1) + 8 * (rl & 1) + g;
            float4 pA = *(const float4*)&partp[row * 8];
            float4 pB = *(const float4*)&partp[row * 8 + 4];
            float s = pA.x + pA.z + pB.x + pB.z;
            float q = pA.y + pA.w + pB.y + pB.w;
            float mean = s * (1.f / 128.f);
            float var = q * (1.f / 128.f) - mean * mean;
            float rsv = rsqrtf(var + 1e-5f);
            float mrs = -mean * rsv;
            rs2[rl] = pk2(rsv, rsv);
            mr2[rl] = pk2(mrs, mrs);
        }
        uint32_t ypk[2][4][2];
#pragma unroll
        for (int mt = 0; mt < 2; mt++)
#pragma unroll
            for (int nt = 0; nt < 4; nt++) {
                int rl0 = 2 * mt, rl1 = 2 * mt + 1;
                ull gg = *(const ull*)&sg2[C0 + 8 * nt + 2 * t];
                ull ee = *(const ull*)&sbe2[C0 + 8 * nt + 2 * t];
                ull y01 = fma2(fma2(accp[mt][nt][0], rs2[rl0], mr2[rl0]), gg, ee);
                ull y23 = fma2(fma2(accp[mt][nt][1], rs2[rl1], mr2[rl1]), gg, ee);
                ypk[mt][nt][0] = silu2bf(y01);
                ypk[mt][nt][1] = silu2bf(y23);
            }

        // ---- GEMM2 from registers: partial X3 for this warp's K-slice ----
        float a3[2][2][4];
#pragma unroll
        for (int mt = 0; mt < 2; mt++)
#pragma unroll
            for (int nb = 0; nb < 2; nb++)
#pragma unroll
                for (int u = 0; u < 4; u++) a3[mt][nb][u] = 0.f;
#pragma unroll
        for (int kb2 = 0; kb2 < 2; kb2++) {
            uint32_t bb[4];
            ldsm4(bb, bAddr3 + kb2 * 32);
#pragma unroll
            for (int mt = 0; mt < 2; mt++) {
                uint32_t af[4] = { ypk[mt][2 * kb2][0], ypk[mt][2 * kb2][1],
                                   ypk[mt][2 * kb2 + 1][0], ypk[mt][2 * kb2 + 1][1] };
                mma16816(a3[mt][0], af, &bb[0]);
                mma16816(a3[mt][1], af, &bb[2]);
            }
        }
        // store bf16 partials: buffer wc, row pitch 10 words
        {
            uint32_t* p3 = P3w + wc * 640;
#pragma unroll
            for (int mt = 0; mt < 2; mt++)
#pragma unroll
                for (int nb = 0; nb < 2; nb++) {
                    int row = R0 + 16 * mt + g;
                    int w = 4 * nb + t;
                    p3[row * 10 + w] = packbf(a3[mt][nb][0], a3[mt][nb][1]);
                    p3[(row + 8) * 10 + w] = packbf(a3[mt][nb][2], a3[mt][nb][3]);
                }
        }

        // ---- prefetch next tile's indices (cp.async, zero reg cost) ----
        {
            int tile_n = tile + EDGE_GRID;
            if (tile_n < NTILES && lane < 6) {
                int en0 = tile_n * MTILE + warp * 8;
                int seg = lane >> 1, half = lane & 1;
                const char* src = seg == 0 ? (const char*)(rowI + en0)
                                : seg == 1 ? (const char*)(colI + en0)
                                           : (const char*)(edge_attr + en0);
                cpa16(idxDst + seg * 32 + half * 16, src + half * 16);
            }
            asm volatile("cp.async.commit_group;" ::: "memory");
        }

        // ---- preload scatter operands so their latency overlaps sync3 ----
        float cd[9]; int r2 = 0; float em = 0.f;
        if (warp == 4 || warp == 5) {
            int el = tid - 128;
            int e2 = ebase + el;
            const float* cdp = coord_diff + (size_t)e2 * 9;
#pragma unroll
            for (int c9 = 0; c9 < 9; c9++) cd[c9] = __ldg(cdp + c9);
            r2 = __ldg(rowI + e2);
            em = __ldg(edge_mask + e2);
        }
        __syncthreads();   // sync3: X3 partials ready

        // ---- scatter (warps 4-5): sum partials, transform, atomics ----
        if (warp == 4 || warp == 5) {
            int el = tid - 128;
            float ph[10];
#pragma unroll
            for (int w = 0; w < 5; w++) {
                ull sacc = add2(add2(bf2f2(P3w[el * 10 + w]), bf2f2(P3w[640 + el * 10 + w])),
                                add2(bf2f2(P3w[1280 + el * 10 + w]), bf2f2(P3w[1920 + el * 10 + w])));
                float2 f = up2(sacc);
                ph[2 * w] = f.x; ph[2 * w + 1] = f.y;
            }
            float* aggp = g_agg + (size_t)r2 * 9;
#pragma unroll
            for (int l = 0; l < 3; l++)
#pragma unroll
                for (int k = 0; k < 3; k++) {
                    float tr = cd[k] * ph[l] + cd[3 + k] * ph[3 + l] + cd[6 + k] * ph[6 + l];
                    atomicAdd(aggp + l * 3 + k, tr * em);
                }
        }
    }
}

__global__ void finalize_kernel(const float* __restrict__ coord,
                                const float* __restrict__ node_mask,
                                float* __restrict__ out) {
    int i4 = blockIdx.x * 256 + threadIdx.x;
    if (i4 < (NNODES * 9) / 4) {     // 450000 = 112500 * 4 exactly
        float4 c = ((const float4*)coord)[i4];
        float4 a = ((const float4*)g_agg)[i4];
        int i = i4 * 4;
        float4 o;
        o.x = (c.x + a.x * 0.01f) * __ldg(node_mask + (i    ) / 9);
        o.y = (c.y + a.y * 0.01f) * __ldg(node_mask + (i + 1) / 9);
        o.z = (c.z + a.z * 0.01f) * __ldg(node_mask + (i + 2) / 9);
        o.w = (c.w + a.w * 0.01f) * __ldg(node_mask + (i + 3) / 9);
        ((float4*)out)[i4] = o;
    }
}

extern "C" void kernel_launch(void* const* d_in, const int* in_sizes, int n_in,
                              void* d_out, int out_size) {
    const float* h          = (const float*)d_in[0];
    const float* coord      = (const float*)d_in[1];
    const float* coord_diff = (const float*)d_in[2];
    const float* edge_attr  = (const float*)d_in[3];
    const float* edge_mask  = (const float*)d_in[4];
    const float* node_mask  = (const float*)d_in[5];
    const int*   rowI       = (const int*)d_in[6];
    const int*   colI       = (const int*)d_in[7];
    const float* W1  = (const float*)d_in[8];
    const float* b1  = (const float*)d_in[9];
    const float* g1  = (const float*)d_in[10];
    const float* be1 = (const float*)d_in[11];
    const float* W2  = (const float*)d_in[12];
    const float* b2  = (const float*)d_in[13];
    const float* g2  = (const float*)d_in[14];
    const float* be2 = (const float*)d_in[15];
    const float* W3  = (const float*)d_in[16];
    float* out = (float*)d_out;

    cudaFuncSetAttribute(hab_kernel, cudaFuncAttributeMaxDynamicSharedMemorySize, HAB_SMEM);
    cudaFuncSetAttribute(edge_kernel, cudaFuncAttributeMaxDynamicSharedMemorySize, EDGE_SMEM);

    prep_kernel<<<(NNODES * 9 + 255) / 256, 256>>>(W1);
    hab_kernel<<<(NNODES + 63) / 64, 256, HAB_SMEM>>>(h, b1);
    edge_kernel<<<EDGE_GRID, 256, EDGE_SMEM>>>(W1, g1, be1, W2, b2, g2, be2, W3,
                                               rowI, colI, edge_attr, edge_mask, coord_diff);
    finalize_kernel<<<((NNODES * 9) / 4 + 255) / 256, 256>>>(coord, node_mask, out);
}

// round 14
// speedup vs baseline: 1.1436x; 1.0511x over previous
#include <cuda_runtime.h>
#include <cuda_bf16.h>
#include <cuda_fp16.h>
#include <stdint.h>

#define NNODES 50000
#define NEDGES 800000
#define MTILE 64
#define NTILES (NEDGES / MTILE)   // 12500
#define EDGE_GRID 444
#define NODE_TILES ((NNODES + 63) / 64)   // 782
#define HAB_GRID 296

typedef unsigned long long ull;

// ---------------- scratch ----------------
__device__ __align__(128) __nv_bfloat16 g_hAB[(size_t)NNODES * 256];
__device__ __align__(128) __nv_bfloat16 g_W1T[2 * 128 * 128];
__device__ float g_sA[NNODES];
__device__ float g_sB[NNODES];
__device__ float g_agg[NNODES * 9];

// ---------------- helpers ----------------
static __device__ __forceinline__ uint32_t packbf(float a, float b) {
    __nv_bfloat162 h = __floats2bfloat162_rn(a, b);
    return *reinterpret_cast<uint32_t*>(&h);
}
// ---- packed f32x2 ----
static __device__ __forceinline__ ull pk2(float lo, float hi) {
    ull r; asm("mov.b64 %0, {%1, %2};" : "=l"(r) : "f"(lo), "f"(hi)); return r;
}
static __device__ __forceinline__ float2 up2(ull v) {
    float2 f; asm("mov.b64 {%0, %1}, %2;" : "=f"(f.x), "=f"(f.y) : "l"(v)); return f;
}
static __device__ __forceinline__ ull add2(ull a, ull b) {
    ull r; asm("add.rn.f32x2 %0, %1, %2;" : "=l"(r) : "l"(a), "l"(b)); return r;
}
static __device__ __forceinline__ ull mul2(ull a, ull b) {
    ull r; asm("mul.rn.f32x2 %0, %1, %2;" : "=l"(r) : "l"(a), "l"(b)); return r;
}
static __device__ __forceinline__ ull fma2(ull a, ull b, ull c) {
    ull r; asm("fma.rn.f32x2 %0, %1, %2, %3;" : "=l"(r) : "l"(a), "l"(b), "l"(c)); return r;
}
// bf16x2 word -> f32x2 (element order preserved)
static __device__ __forceinline__ ull bf2f2(uint32_t u) {
    uint32_t lo = u << 16;
    uint32_t hi = u & 0xFFFF0000u;
    ull r; asm("mov.b64 %0, {%1, %2};" : "=l"(r) : "r"(lo), "r"(hi)); return r;
}

static __device__ __forceinline__ void mma16816(float* c, const uint32_t* a, const uint32_t* b) {
    asm volatile(
        "mma.sync.aligned.m16n8k16.row.col.f32.bf16.bf16.f32 "
        "{%0,%1,%2,%3}, {%4,%5,%6,%7}, {%8,%9}, {%0,%1,%2,%3};\n"
        : "+f"(c[0]), "+f"(c[1]), "+f"(c[2]), "+f"(c[3])
        : "r"(a[0]), "r"(a[1]), "r"(a[2]), "r"(a[3]), "r"(b[0]), "r"(b[1]));
}
static __device__ __forceinline__ void ldsm4(uint32_t* r, uint32_t addr) {
    asm volatile("ldmatrix.sync.aligned.m8n8.x4.shared.b16 {%0,%1,%2,%3}, [%4];"
        : "=r"(r[0]), "=r"(r[1]), "=r"(r[2]), "=r"(r[3]) : "r"(addr));
}
// silu on a packed f32x2, computed natively in bf16x2, returns bf16x2 word
static __device__ __forceinline__ uint32_t silu2bf(ull y2) {
    float2 yf = up2(y2);
    uint32_t yb, hb, tb, rb;
    asm("cvt.rn.bf16x2.f32 %0, %1, %2;" : "=r"(yb) : "f"(yf.y), "f"(yf.x));
    asm("mul.rn.bf16x2 %0, %1, %2;" : "=r"(hb) : "r"(yb), "r"(0x3F003F00u));
    asm("tanh.approx.bf16x2 %0, %1;" : "=r"(tb) : "r"(hb));
    asm("fma.rn.bf16x2 %0, %1, %2, %3;" : "=r"(rb) : "r"(hb), "r"(tb), "r"(hb));
    return rb;
}
static __device__ __forceinline__ uint32_t s2u(const void* p) {
    return (uint32_t)__cvta_generic_to_shared(p);
}
static __device__ __forceinline__ void cpa16(uint32_t dst, const void* src) {
    asm volatile("cp.async.ca.shared.global [%0], [%1], 16;" :: "r"(dst), "l"(src));
}

// ---------------------------------------------------------------------------
// prep: W1 -> bf16 transposed halves (coalesced writes); zero agg
// ---------------------------------------------------------------------------
__global__ void prep_kernel(const float* __restrict__ W1) {
    int i = blockIdx.x * 256 + threadIdx.x;
    if (i < 2 * 128 * 128) {
        int hb = i >> 14, n = (i >> 7) & 127, k = i & 127;
        g_W1T[i] = __float2bfloat16(W1[(size_t)(hb * 128 + k) * 128 + n]);
    }
    if (i < NNODES * 9) g_agg[i] = 0.f;
}

// ---------------------------------------------------------------------------
// hab (PERSISTENT): W1T staged once per block; grid-stride over node tiles.
// hA' = h@W1[0:128]+b1 ; hB = h@W1[128:256]; row sums to g_sA/g_sB.
// grid 296, block 256, occ 2.
// ---------------------------------------------------------------------------
#define HAB_SMEM (17408 + 2 * 34816 + 2048)   // 89856
__global__ void __launch_bounds__(256, 2)
hab_kernel(const float* __restrict__ h, const float* __restrict__ b1) {
    extern __shared__ unsigned char sm[];
    unsigned char* smA = sm;                    // 64 x 272B
    unsigned char* smB = sm + 17408;            // 2 x (128 x 272B)
    float* part = (float*)(sm + 17408 + 2 * 34816);  // 2 x (64 x 4) floats

    const int tid = threadIdx.x;

    // stage both W1T halves ONCE (uint4, conflict-light)
    for (int idx = tid; idx < 2 * 128 * 16; idx += 256) {
        int hb = idx >> 11, rem = idx & 2047;
        int n = rem >> 4, q = rem & 15;
        *(uint4*)(smB + hb * 34816 + n * 272 + q * 16) =
            ((const uint4*)(g_W1T + (hb << 14)))[rem];
    }

    const int warp = tid >> 5, lane = tid & 31;
    const int lr = lane & 7, sel = lane >> 3, g = lane >> 2, t = lane & 3;
    const int R0 = (warp & 1) * 32, wc = warp >> 1, C0 = wc * 32;

    uint32_t aAddr[2], bAddr[2];
#pragma unroll
    for (int mt = 0; mt < 2; mt++)
        aAddr[mt] = s2u(smA + (R0 + 16 * mt + lr + (sel & 1) * 8) * 272 + (sel >> 1) * 16);
#pragma unroll
    for (int np = 0; np < 2; np++)
        bAddr[np] = s2u(smB + (C0 + 16 * np + lr + (sel >> 1) * 8) * 272 + (sel & 1) * 16);

    float b1v0[8], b1v1[8];
#pragma unroll
    for (int nt = 0; nt < 4; nt++) {
        b1v0[2 * nt] = b1[C0 + 8 * nt + 2 * t];
        b1v0[2 * nt + 1] = b1[C0 + 8 * nt + 2 * t + 1];
        b1v1[2 * nt] = 0.f; b1v1[2 * nt + 1] = 0.f;
    }

    uint32_t* outw = (uint32_t*)g_hAB;

    for (int ntile = blockIdx.x; ntile < NODE_TILES; ntile += HAB_GRID) {
        const int nt0 = ntile * 64;

        // stage h tile (barrier also orders prior part-reads before new writes)
        for (int idx = tid; idx < 64 * 32; idx += 256) {
            int i = idx >> 5, kq = idx & 31;
            float4 v = make_float4(0.f, 0.f, 0.f, 0.f);
            if (nt0 + i < NNODES) v = *(const float4*)(h + (size_t)(nt0 + i) * 128 + kq * 4);
            *(uint2*)(smA + i * 272 + kq * 8) = make_uint2(packbf(v.x, v.y), packbf(v.z, v.w));
        }
        __syncthreads();   // sync1: smA (and on iter 0, smB) ready

#pragma unroll
        for (int hb = 0; hb < 2; hb++) {
            float acc[2][4][4];
#pragma unroll
            for (int mt = 0; mt < 2; mt++)
#pragma unroll
                for (int nt = 0; nt < 4; nt++)
#pragma unroll
                    for (int u = 0; u < 4; u++) acc[mt][nt][u] = 0.f;

#pragma unroll
            for (int kb = 0; kb < 8; kb++) {
                uint32_t a[2][4], b[2][4];
                ldsm4(a[0], aAddr[0] + kb * 32);
                ldsm4(a[1], aAddr[1] + kb * 32);
                ldsm4(b[0], bAddr[0] + hb * 34816 + kb * 32);
                ldsm4(b[1], bAddr[1] + hb * 34816 + kb * 32);
#pragma unroll
                for (int mt = 0; mt < 2; mt++)
#pragma unroll
                    for (int np = 0; np < 2; np++) {
                        mma16816(acc[mt][2 * np], a[mt], &b[np][0]);
                        mma16816(acc[mt][2 * np + 1], a[mt], &b[np][2]);
                    }
            }

            const float* b1v = hb == 0 ? b1v0 : b1v1;
            float ps[4] = {0.f, 0.f, 0.f, 0.f};
#pragma unroll
            for (int mt = 0; mt < 2; mt++)
#pragma unroll
                for (int nt = 0; nt < 4; nt++) {
                    float v0 = acc[mt][nt][0] + b1v[2 * nt];
                    float v1 = acc[mt][nt][1] + b1v[2 * nt + 1];
                    float v2 = acc[mt][nt][2] + b1v[2 * nt];
                    float v3 = acc[mt][nt][3] + b1v[2 * nt + 1];
                    ps[2 * mt] += v0 + v1;
                    ps[2 * mt + 1] += v2 + v3;
                    int node0 = nt0 + R0 + 16 * mt + g;
                    int cc = C0 + 8 * nt + 2 * t;
                    if (node0 < NNODES)
                        outw[((size_t)node0 * 256 + (hb << 7) + cc) >> 1] = packbf(v0, v1);
                    if (node0 + 8 < NNODES)
                        outw[((size_t)(node0 + 8) * 256 + (hb << 7) + cc) >> 1] = packbf(v2, v3);
                }
#pragma unroll
            for (int rl = 0; rl < 4; rl++) {
                ps[rl] += __shfl_xor_sync(0xffffffffu, ps[rl], 1);
                ps[rl] += __shfl_xor_sync(0xffffffffu, ps[rl], 2);
            }
            if (t == 0) {
#pragma unroll
                for (int rl = 0; rl < 4; rl++) {
                    int row = R0 + 16 * (rl >> 1) + 8 * (rl & 1) + g;
                    part[hb * 256 + row * 4 + wc] = ps[rl];
                }
            }
        }
        __syncthreads();   // sync2: part ready; smA reads done
        if (tid < 64) {
            int node = nt0 + tid;
            if (node < NNODES) {
                g_sA[node] = part[tid * 4] + part[tid * 4 + 1]
                           + part[tid * 4 + 2] + part[tid * 4 + 3];
                g_sB[node] = part[256 + tid * 4] + part[256 + tid * 4 + 1]
                           + part[256 + tid * 4 + 2] + part[256 + tid * 4 + 3];
            }
        }
    }
}

// ---------------------------------------------------------------------------
// edge kernel (occ 3): 3-barrier pipeline, register GEMM2, bf16x2 silu,
// cp.async index prefetch + full-depth Stage A preload
// ---------------------------------------------------------------------------
#define OFF_XA   0                 // 64 x 272B  (X1 only)
#define OFF_W2   17408             // 128 x 272B
#define OFF_W3   52224             // 16 x 272B
#define OFF_P3   56576             // 4 x 64 x 40B  X3 bf16 partials per warp-col
#define OFF_PART 66816             // 64 x 8 f32 (LN2 stats partials)
#define OFF_PAR  68864             // params (3648B)
#define OFF_IDX  72512             // 8 warps x 96B prefetched indices
#define EDGE_SMEM 73280

__global__ void __launch_bounds__(256, 3)
edge_kernel(const float* __restrict__ W1, const float* __restrict__ g1,
            const float* __restrict__ be1,
            const float* __restrict__ W2, const float* __restrict__ b2,
            const float* __restrict__ g2, const float* __restrict__ be2,
            const float* __restrict__ W3,
            const int* __restrict__ rowI, const int* __restrict__ colI,
            const float* __restrict__ edge_attr, const float* __restrict__ edge_mask,
            const float* __restrict__ coord_diff) {
    extern __shared__ unsigned char sm[];
    unsigned char* smXA = sm + OFF_XA;
    uint32_t* XAw = (uint32_t*)smXA;
    __nv_bfloat16* W2h = (__nv_bfloat16*)(sm + OFF_W2);
    __nv_bfloat16* W3h = (__nv_bfloat16*)(sm + OFF_W3);
    uint32_t* P3w = (uint32_t*)(sm + OFF_P3);          // [wc][row][10 words]
    float* partp = (float*)(sm + OFF_PART);
    float* par = (float*)(sm + OFF_PAR);
    float* sw1c = par;           float* sg1 = par + 128;  float* sbe1 = par + 256;
    float* sb2 = par + 384;      float* sg2 = par + 512;  float* sbe2 = par + 640;
    float* sSw = par + 768;

    const int tid = threadIdx.x;
    if (tid < 128) {
        sw1c[tid] = W1[256 * 128 + tid];
        sg1[tid] = g1[tid]; sbe1[tid] = be1[tid];
        sb2[tid] = b2[tid]; sg2[tid] = g2[tid]; sbe2[tid] = be2[tid];
    }
    for (int idx = tid; idx < 128 * 128; idx += 256) {
        int k = idx >> 7, n = idx & 127;
        W2h[n * 136 + k] = __float2bfloat16(W2[idx]);
    }
    for (int idx = tid; idx < 16 * 128; idx += 256) {
        int n = idx >> 7, k = idx & 127;
        W3h[n * 136 + k] = __float2bfloat16(n < 9 ? W3[k * 9 + n] : 0.f);
    }
    __syncthreads();

    const int warp = tid >> 5, lane = tid & 31;
    const int lr = lane & 7, sel = lane >> 3, g = lane >> 2, t = lane & 3;
    const int R0 = (warp & 1) * 32, wc = warp >> 1, C0 = wc * 32;
    const int j0 = lane * 4;

    if (warp == 0) {
        float s = sw1c[lane] + sw1c[lane + 32] + sw1c[lane + 64] + sw1c[lane + 96];
#pragma unroll
        for (int o = 16; o > 0; o >>= 1) s += __shfl_xor_sync(0xffffffffu, s, o);
        if (lane == 0) sSw[0] = s;
    }
    __syncthreads();

    // packed per-lane LN1 parameters
    const ull w01  = *(const ull*)&sw1c[j0],  w23  = *(const ull*)&sw1c[j0 + 2];
    const ull g01  = *(const ull*)&sg1[j0],   g23  = *(const ull*)&sg1[j0 + 2];
    const ull be01 = *(const ull*)&sbe1[j0],  be23 = *(const ull*)&sbe1[j0 + 2];
    const float Sw = sSw[0];

    // ldmatrix base addresses
    uint32_t aAddr[2], bAddr[2];
#pragma unroll
    for (int mt = 0; mt < 2; mt++)
        aAddr[mt] = s2u(smXA + (R0 + 16 * mt + lr + (sel & 1) * 8) * 272 + (sel >> 1) * 16);
#pragma unroll
    for (int np = 0; np < 2; np++)
        bAddr[np] = s2u(sm + OFF_W2 + (C0 + 16 * np + lr + (sel >> 1) * 8) * 272 + (sel & 1) * 16);
    const uint32_t bAddr3 = s2u(sm + OFF_W3 + (lr + (sel >> 1) * 8) * 272 + (sel & 1) * 16) + wc * 64;

    const uint32_t idxDst = s2u(sm + OFF_IDX) + warp * 96;
    const int* idxR = (const int*)(sm + OFF_IDX + warp * 96);
    const int* idxC = idxR + 8;
    const float* idxE = (const float*)(idxR + 16);

    // prefetch indices for the first tile
    {
        int en0 = blockIdx.x * MTILE + warp * 8;
        if (lane < 6) {
            int seg = lane >> 1, half = lane & 1;
            const char* src = seg == 0 ? (const char*)(rowI + en0)
                            : seg == 1 ? (const char*)(colI + en0)
                                       : (const char*)(edge_attr + en0);
            cpa16(idxDst + seg * 32 + half * 16, src + half * 16);
        }
        asm volatile("cp.async.commit_group;" ::: "memory");
    }

    for (int tile = blockIdx.x; tile < NTILES; tile += EDGE_GRID) {
        const int ebase = tile * MTILE;

        // ---- Stage A: idx from smem, full-depth gather preload, LN1+SiLU ----
        asm volatile("cp.async.wait_group 0;" ::: "memory");
        __syncwarp();
        int rs8[8], cs8[8]; float eas[8];
#pragma unroll
        for (int it = 0; it < 8; it++) {
            rs8[it] = idxR[it]; cs8[it] = idxC[it]; eas[it] = idxE[it];
        }
        uint2 pwa[8], pwb[8]; float psa[8], psb[8];
#pragma unroll
        for (int it = 0; it < 8; it++) {
            pwa[it] = *(const uint2*)(g_hAB + (size_t)rs8[it] * 256 + j0);
            pwb[it] = *(const uint2*)(g_hAB + (size_t)cs8[it] * 256 + 128 + j0);
            psa[it] = __ldg(g_sA + rs8[it]);
            psb[it] = __ldg(g_sB + cs8[it]);
        }
#pragma unroll
        for (int it = 0; it < 8; it++) {
            float ea = eas[it];
            ull a01 = bf2f2(pwa[it].x), a23 = bf2f2(pwa[it].y);
            ull f01 = bf2f2(pwb[it].x), f23 = bf2f2(pwb[it].y);
            ull ea2 = pk2(ea, ea);
            ull x01 = fma2(ea2, w01, add2(a01, f01));
            ull x23 = fma2(ea2, w23, add2(a23, f23));
            ull q2 = fma2(x01, x01, mul2(x23, x23));
            float2 qf = up2(q2);
            float q = qf.x + qf.y;
#pragma unroll
            for (int o = 16; o > 0; o >>= 1) q += __shfl_xor_sync(0xffffffffu, q, o);
            float mean = (psa[it] + psb[it] + ea * Sw) * (1.f / 128.f);
            float var = q * (1.f / 128.f) - mean * mean;
            float rsv = rsqrtf(var + 1e-5f);
            float mrs = -mean * rsv;
            ull rsv2 = pk2(rsv, rsv), mrs2 = pk2(mrs, mrs);
            ull y01 = fma2(fma2(x01, rsv2, mrs2), g01, be01);
            ull y23 = fma2(fma2(x23, rsv2, mrs2), g23, be23);
            *(uint2*)&XAw[(warp * 8 + it) * 68 + lane * 2] =
                make_uint2(silu2bf(y01), silu2bf(y23));
        }
        __syncthreads();   // sync1: X1 ready

        // ---- GEMM1: acc = X1 @ W2 ----
        float acc[2][4][4];
#pragma unroll
        for (int mt = 0; mt < 2; mt++)
#pragma unroll
            for (int nt = 0; nt < 4; nt++)
#pragma unroll
                for (int u = 0; u < 4; u++) acc[mt][nt][u] = 0.f;
#pragma unroll
        for (int kb = 0; kb < 8; kb++) {
            uint32_t a[2][4], b[2][4];
            ldsm4(a[0], aAddr[0] + kb * 32);
            ldsm4(a[1], aAddr[1] + kb * 32);
            ldsm4(b[0], bAddr[0] + kb * 32);
            ldsm4(b[1], bAddr[1] + kb * 32);
#pragma unroll
            for (int mt = 0; mt < 2; mt++)
#pragma unroll
                for (int np = 0; np < 2; np++) {
                    mma16816(acc[mt][2 * np], a[mt], &b[np][0]);
                    mma16816(acc[mt][2 * np + 1], a[mt], &b[np][2]);
                }
        }
        // bias + per-row partial sums (for LN2), packed f32x2
        ull accp[2][4][2];
        ull psA[4], pqA[4];
#pragma unroll
        for (int rl = 0; rl < 4; rl++) { psA[rl] = 0ull; pqA[rl] = 0ull; }
#pragma unroll
        for (int mt = 0; mt < 2; mt++)
#pragma unroll
            for (int nt = 0; nt < 4; nt++) {
                ull bb = *(const ull*)&sb2[C0 + 8 * nt + 2 * t];
                ull v01 = add2(pk2(acc[mt][nt][0], acc[mt][nt][1]), bb);
                ull v23 = add2(pk2(acc[mt][nt][2], acc[mt][nt][3]), bb);
                accp[mt][nt][0] = v01; accp[mt][nt][1] = v23;
                psA[2 * mt] = add2(psA[2 * mt], v01);
                pqA[2 * mt] = fma2(v01, v01, pqA[2 * mt]);
                psA[2 * mt + 1] = add2(psA[2 * mt + 1], v23);
                pqA[2 * mt + 1] = fma2(v23, v23, pqA[2 * mt + 1]);
            }
        float ps[4], pq[4];
#pragma unroll
        for (int rl = 0; rl < 4; rl++) {
            float2 pf = up2(psA[rl]); ps[rl] = pf.x + pf.y;
            float2 qf = up2(pqA[rl]); pq[rl] = qf.x + qf.y;
            ps[rl] += __shfl_xor_sync(0xffffffffu, ps[rl], 1);
            ps[rl] += __shfl_xor_sync(0xffffffffu, ps[rl], 2);
            pq[rl] += __shfl_xor_sync(0xffffffffu, pq[rl], 1);
            pq[rl] += __shfl_xor_sync(0xffffffffu, pq[rl], 2);
        }
        if (t == 0) {
#pragma unroll
            for (int rl = 0; rl < 4; rl++) {
                int row = R0 + 16 * (rl >> 1) + 8 * (rl & 1) + g;
                *(float2*)&partp[row * 8 + wc * 2] = make_float2(ps[rl], pq[rl]);
            }
        }
        __syncthreads();   // sync2: stats partials ready

        // ---- LN2 + SiLU in registers -> A-fragments ypk (bf16x2) ----
        ull rs2[4], mr2[4];
#pragma unroll
        for (int rl = 0; rl < 4; rl++) {
            int row = R0 + 16 * (rl >> 1) + 8 * (rl & 1) + g;
            float4 pA = *(const float4*)&partp[row * 8];
            float4 pB = *(const float4*)&partp[row * 8 + 4];
            float s = pA.x + pA.z + pB.x + pB.z;
            float q = pA.y + pA.w + pB.y + pB.w;
            float mean = s * (1.f / 128.f);
            float var = q * (1.f / 128.f) - mean * mean;
            float rsv = rsqrtf(var + 1e-5f);
            float mrs = -mean * rsv;
            rs2[rl] = pk2(rsv, rsv);
            mr2[rl] = pk2(mrs, mrs);
        }
        uint32_t ypk[2][4][2];
#pragma unroll
        for (int mt = 0; mt < 2; mt++)
#pragma unroll
            for (int nt = 0; nt < 4; nt++) {
                int rl0 = 2 * mt, rl1 = 2 * mt + 1;
                ull gg = *(const ull*)&sg2[C0 + 8 * nt + 2 * t];
                ull ee = *(const ull*)&sbe2[C0 + 8 * nt + 2 * t];
                ull y01 = fma2(fma2(accp[mt][nt][0], rs2[rl0], mr2[rl0]), gg, ee);
                ull y23 = fma2(fma2(accp[mt][nt][1], rs2[rl1], mr2[rl1]), gg, ee);
                ypk[mt][nt][0] = silu2bf(y01);
                ypk[mt][nt][1] = silu2bf(y23);
            }

        // ---- GEMM2 from registers: partial X3 for this warp's K-slice ----
        float a3[2][2][4];
#pragma unroll
        for (int mt = 0; mt < 2; mt++)
#pragma unroll
            for (int nb = 0; nb < 2; nb++)
#pragma unroll
                for (int u = 0; u < 4; u++) a3[mt][nb][u] = 0.f;
#pragma unroll
        for (int kb2 = 0; kb2 < 2; kb2++) {
            uint32_t bb[4];
            ldsm4(bb, bAddr3 + kb2 * 32);
#pragma unroll
            for (int mt = 0; mt < 2; mt++) {
                uint32_t af[4] = { ypk[mt][2 * kb2][0], ypk[mt][2 * kb2][1],
                                   ypk[mt][2 * kb2 + 1][0], ypk[mt][2 * kb2 + 1][1] };
                mma16816(a3[mt][0], af, &bb[0]);
                mma16816(a3[mt][1], af, &bb[2]);
            }
        }
        // store bf16 partials: buffer wc, row pitch 10 words
        {
            uint32_t* p3 = P3w + wc * 640;
#pragma unroll
            for (int mt = 0; mt < 2; mt++)
#pragma unroll
                for (int nb = 0; nb < 2; nb++) {
                    int row = R0 + 16 * mt + g;
                    int w = 4 * nb + t;
                    p3[row * 10 + w] = packbf(a3[mt][nb][0], a3[mt][nb][1]);
                    p3[(row + 8) * 10 + w] = packbf(a3[mt][nb][2], a3[mt][nb][3]);
                }
        }

        // ---- prefetch next tile's indices (cp.async, zero reg cost) ----
        {
            int tile_n = tile + EDGE_GRID;
            if (tile_n < NTILES && lane < 6) {
                int en0 = tile_n * MTILE + warp * 8;
                int seg = lane >> 1, half = lane & 1;
                const char* src = seg == 0 ? (const char*)(rowI + en0)
                                : seg == 1 ? (const char*)(colI + en0)
                                           : (const char*)(edge_attr + en0);
                cpa16(idxDst + seg * 32 + half * 16, src + half * 16);
            }
            asm volatile("cp.async.commit_group;" ::: "memory");
        }

        // ---- preload scatter operands so their latency overlaps sync3 ----
        float cd[9]; int r2 = 0; float em = 0.f;
        if (warp == 4 || warp == 5) {
            int el = tid - 128;
            int e2 = ebase + el;
            const float* cdp = coord_diff + (size_t)e2 * 9;
#pragma unroll
            for (int c9 = 0; c9 < 9; c9++) cd[c9] = __ldg(cdp + c9);
            r2 = __ldg(rowI + e2);
            em = __ldg(edge_mask + e2);
        }
        __syncthreads();   // sync3: X3 partials ready

        // ---- scatter (warps 4-5): sum partials, transform, atomics ----
        if (warp == 4 || warp == 5) {
            int el = tid - 128;
            float ph[10];
#pragma unroll
            for (int w = 0; w < 5; w++) {
                ull sacc = add2(add2(bf2f2(P3w[el * 10 + w]), bf2f2(P3w[640 + el * 10 + w])),
                                add2(bf2f2(P3w[1280 + el * 10 + w]), bf2f2(P3w[1920 + el * 10 + w])));
                float2 f = up2(sacc);
                ph[2 * w] = f.x; ph[2 * w + 1] = f.y;
            }
            float* aggp = g_agg + (size_t)r2 * 9;
#pragma unroll
            for (int l = 0; l < 3; l++)
#pragma unroll
                for (int k = 0; k < 3; k++) {
                    float tr = cd[k] * ph[l] + cd[3 + k] * ph[3 + l] + cd[6 + k] * ph[6 + l];
                    atomicAdd(aggp + l * 3 + k, tr * em);
                }
        }
    }
}

__global__ void finalize_kernel(const float* __restrict__ coord,
                                const float* __restrict__ node_mask,
                                float* __restrict__ out) {
    int i4 = blockIdx.x * 256 + threadIdx.x;
    if (i4 < (NNODES * 9) / 4) {     // 450000 = 112500 * 4 exactly
        float4 c = ((const float4*)coord)[i4];
        float4 a = ((const float4*)g_agg)[i4];
        int i = i4 * 4;
        float4 o;
        o.x = (c.x + a.x * 0.01f) * __ldg(node_mask + (i    ) / 9);
        o.y = (c.y + a.y * 0.01f) * __ldg(node_mask + (i + 1) / 9);
        o.z = (c.z + a.z * 0.01f) * __ldg(node_mask + (i + 2) / 9);
        o.w = (c.w + a.w * 0.01f) * __ldg(node_mask + (i + 3) / 9);
        ((float4*)out)[i4] = o;
    }
}

extern "C" void kernel_launch(void* const* d_in, const int* in_sizes, int n_in,
                              void* d_out, int out_size) {
    const float* h          = (const float*)d_in[0];
    const float* coord      = (const float*)d_in[1];
    const float* coord_diff = (const float*)d_in[2];
    const float* edge_attr  = (const float*)d_in[3];
    const float* edge_mask  = (const float*)d_in[4];
    const float* node_mask  = (const float*)d_in[5];
    const int*   rowI       = (const int*)d_in[6];
    const int*   colI       = (const int*)d_in[7];
    const float* W1  = (const float*)d_in[8];
    const float* b1  = (const float*)d_in[9];
    const float* g1  = (const float*)d_in[10];
    const float* be1 = (const float*)d_in[11];
    const float* W2  = (const float*)d_in[12];
    const float* b2  = (const float*)d_in[13];
    const float* g2  = (const float*)d_in[14];
    const float* be2 = (const float*)d_in[15];
    const float* W3  = (const float*)d_in[16];
    float* out = (float*)d_out;

    cudaFuncSetAttribute(hab_kernel, cudaFuncAttributeMaxDynamicSharedMemorySize, HAB_SMEM);
    cudaFuncSetAttribute(edge_kernel, cudaFuncAttributeMaxDynamicSharedMemorySize, EDGE_SMEM);

    prep_kernel<<<(NNODES * 9 + 255) / 256, 256>>>(W1);
    hab_kernel<<<HAB_GRID, 256, HAB_SMEM>>>(h, b1);
    edge_kernel<<<EDGE_GRID, 256, EDGE_SMEM>>>(W1, g1, be1, W2, b2, g2, be2, W3,
                                               rowI, colI, edge_attr, edge_mask, coord_diff);
    finalize_kernel<<<((NNODES * 9) / 4 + 255) / 256, 256>>>(coord, node_mask, out);
}